// round 10
// baseline (speedup 1.0000x reference)
#include <cuda_runtime.h>
#include <cuda.h>
#include <cuda_fp16.h>
#include <cstdint>
#include <cstddef>

// ============================================================================
// Device scratch (allocation-free rule: static __device__ globals)
// ============================================================================
static __device__ __align__(1024) __half g_Xh[8192ull * 4096ull];   // 64 MB
static __device__ __align__(1024) __half g_Wh[4096ull * 4096ull];   // 32 MB

// ============================================================================
// Baseline-PTX helpers (harness assembles for sm_103 WITHOUT 'a' ->
// no tcgen05/TMEM/cg2). sm_80-era PTX: cp.async, ldmatrix, mma.sync.
// ============================================================================
__device__ __forceinline__ uint32_t smem_u32(const void* p) {
    uint32_t a;
    asm("{ .reg .u64 t; cvta.to.shared.u64 t, %1; cvt.u32.u64 %0, t; }"
        : "=r"(a) : "l"(p));
    return a;
}

#define CP_ASYNC16(dst, src) \
    asm volatile("cp.async.cg.shared.global [%0], [%1], 16;" \
        :: "r"(dst), "l"(src) : "memory")

#define CP_COMMIT() asm volatile("cp.async.commit_group;" ::: "memory")

#define CP_WAIT1() asm volatile("cp.async.wait_group 1;" ::: "memory")

#define LDSM_X4(r0, r1, r2, r3, addr) \
    asm volatile("ldmatrix.sync.aligned.m8n8.x4.shared.b16 {%0,%1,%2,%3}, [%4];" \
        : "=r"(r0), "=r"(r1), "=r"(r2), "=r"(r3) : "r"(addr))

#define MMA16816(c0, c1, c2, c3, a0, a1, a2, a3, b0, b1)                        \
    asm volatile(                                                               \
        "mma.sync.aligned.m16n8k16.row.col.f32.f16.f16.f32 "                    \
        "{%0,%1,%2,%3}, {%4,%5,%6,%7}, {%8,%9}, {%0,%1,%2,%3};"                 \
        : "+f"(c0), "+f"(c1), "+f"(c2), "+f"(c3)                                \
        : "r"(a0), "r"(a1), "r"(a2), "r"(a3), "r"(b0), "r"(b1))

// ============================================================================
// Kernel 1: NVFP4 quantize->dequantize (fp32 in, fp16 out), 32-elem blocks.
// R9 profile: issue-bound (issue 78.9%, alu 46.5%, DRAM only 36.9%) -- the
// __fdiv_rn subroutines dominated. Replaced with 1x rcp.approx + FMULs:
// the quant DECISION can only flip for elements within ~1e-7 of a threshold
// (negligible, bounded effect), and s1 = a*RN(1/6) is <=1ulp off the
// reference's RN(a/6) -- both invisible under the 2.4e-4 fp16 rounding
// already carried. Layout unchanged: warp-iter = 128 consecutive floats
// (LDG.128/lane), 32-block = 8 lanes, 3-shfl segment reduce, STG.64 out.
// ============================================================================
__global__ void __launch_bounds__(256) nvfp4_qdq_kernel(
    const float4* __restrict__ in4, uint2* __restrict__ out2, int nchunks)
{
    const int lane = threadIdx.x & 31;
    const int warp = blockIdx.x * (blockDim.x >> 5) + (threadIdx.x >> 5);
    const int nwarps = gridDim.x * (blockDim.x >> 5);

    for (int c = warp; c < nchunks; c += nwarps) {           // chunk = 128 floats
        const float4 v = in4[(size_t)c * 32 + lane];
        float a = fmaxf(fmaxf(fabsf(v.x), fabsf(v.y)),
                        fmaxf(fabsf(v.z), fabsf(v.w)));
        a = fmaxf(a, __shfl_xor_sync(0xFFFFFFFFu, a, 4));
        a = fmaxf(a, __shfl_xor_sync(0xFFFFFFFFu, a, 2));
        a = fmaxf(a, __shfl_xor_sync(0xFFFFFFFFu, a, 1));
        const float s1 = fmaxf(a, 1e-12f) * 0.16666667f;     // ~RN(a/6), <=1ulp off
        const float dv = fmaxf(s1, 1e-12f);
        float rc;
        asm("rcp.approx.f32 %0, %1;" : "=f"(rc) : "f"(dv));  // 1 MUFU for 4 elems

        const float xv[4] = {v.x, v.y, v.z, v.w};
        uint16_t h[4];
        #pragma unroll
        for (int u = 0; u < 4; ++u) {
            float xs = xv[u] * rc;
            xs = fminf(fmaxf(xs, -6.0f), 6.0f);
            const float sgn = (xs >= 0.0f) ? 1.0f : -1.0f;
            const float aa = fabsf(xs);
            const float qa =
                aa < 0.25f ? 0.0f :
                aa < 0.75f ? 0.5f :
                aa < 1.25f ? 1.0f :
                aa < 1.75f ? 1.5f :
                aa < 2.5f  ? 2.0f :
                aa < 3.5f  ? 3.0f :
                aa < 5.0f  ? 4.0f : 6.0f;
            h[u] = __half_as_ushort(__float2half_rn(sgn * qa * s1));
        }
        uint2 o;
        o.x = (uint32_t)h[0] | ((uint32_t)h[1] << 16);
        o.y = (uint32_t)h[2] | ((uint32_t)h[3] << 16);
        out2[(size_t)c * 32 + lane] = o;
    }
}

// ============================================================================
// Kernel 2: fp16 GEMM via mma.sync.m16n8k16 (baseline PTX; no tcgen05).
//   D[M,N] = Xh[M,K] * Wh[N,K]^T, fp32 out.
// CTA tile 256x128 (M x N), 256 thr = 8 warps (4m x 2n), warp tile 64x64:
// per ks-step 32 MMAs per 8 LDSM (2x the MMA density of the 128x128 R9
// config -> fewer issue bubbles per HMMA), per-FLOP sync count halved,
// L2 tile traffic halved. K-chunk 64 (128B rows, 8-row XOR swizzle),
// 3-stage cp.async pipeline, 144 KB smem, 1 CTA/SM (acc=128 regs).
// ============================================================================
static constexpr int TM = 256;
static constexpr int TN = 128;
static constexpr int KC = 64;                       // K elems per stage
static constexpr int STAGES = 3;
static constexpr int AT_BYTES = TM * KC * 2;        // 32768
static constexpr int BT_BYTES = TN * KC * 2;        // 16384
static constexpr int STG_BYTES = AT_BYTES + BT_BYTES;   // 49152 (A then B)
static constexpr int SMEM_NEEDED = STAGES * STG_BYTES;  // 147456

__global__ void __launch_bounds__(256, 1) nvfp4_gemm_hmma_kernel(
    float* __restrict__ out,
    const __half* __restrict__ A,   // [M,K]
    const __half* __restrict__ B,   // [N,K]
    int M, int N, int K)
{
    extern __shared__ char dyn_smem[];
    const uint32_t sbase = smem_u32(dyn_smem);

    const int tid  = threadIdx.x;
    const int lane = tid & 31;
    const int wid  = tid >> 5;
    const int wm   = wid & 3;          // 4 warps along M (64 rows each)
    const int wn   = wid >> 2;         // 2 warps along N (64 cols each)
    const int m0   = blockIdx.x * TM;
    const int n0   = blockIdx.y * TN;
    const int kiters = K / KC;         // 64
    const size_t rowK2 = (size_t)K * 2;

    // ---- loader: thread t covers row (t>>3)+32p, 16B chunk (t&7).
    // A: p 0..7 (256 rows), B: p 0..3 (128 rows). Swizzle XOR depends only
    // on row&7 = ldRow0&7 (32p doesn't change low bits) -> +p*4096 strides.
    const int ldRow0 = tid >> 3;
    const int ldC16  = (tid & 7) * 16;
    const char* gA = (const char*)A + (size_t)(m0 + ldRow0) * rowK2 + ldC16;
    const char* gB = (const char*)B + (size_t)(n0 + ldRow0) * rowK2 + ldC16;
    const uint32_t stA0 = (uint32_t)(ldRow0 * 128 + (ldC16 ^ ((ldRow0 & 7) << 4)));
    const size_t pStride = (size_t)32 * rowK2;

    // ---- ldmatrix constants (x4: lanes 0-15 rows @+0, 16-31 @+16B)
    const int fRow = lane & 15;
    const uint32_t kSel = (uint32_t)((lane >> 4) * 16);
    uint32_t aOff[4], aXor[4];
    #pragma unroll
    for (int mt = 0; mt < 4; ++mt) {
        const int r = wm * 64 + mt * 16 + fRow;
        aOff[mt] = (uint32_t)(r * 128);
        aXor[mt] = (uint32_t)((r & 7) << 4);
    }
    uint32_t bOff[4], bXor[4];
    #pragma unroll
    for (int np = 0; np < 4; ++np) {
        const int r = wn * 64 + np * 16 + fRow;
        bOff[np] = (uint32_t)(r * 128);
        bXor[np] = (uint32_t)((r & 7) << 4);
    }

    float acc[4][8][4];
    #pragma unroll
    for (int mt = 0; mt < 4; ++mt)
        #pragma unroll
        for (int nt = 0; nt < 8; ++nt)
            #pragma unroll
            for (int q = 0; q < 4; ++q) acc[mt][nt][q] = 0.0f;

    // ---- prologue: fill stages 0,1
    #pragma unroll
    for (int s = 0; s < 2; ++s) {
        const uint32_t sb = sbase + s * STG_BYTES;
        const size_t kB = (size_t)s * 128;
        #pragma unroll
        for (int p = 0; p < 8; ++p)
            CP_ASYNC16(sb + stA0 + p * 4096, gA + kB + p * pStride);
        #pragma unroll
        for (int p = 0; p < 4; ++p)
            CP_ASYNC16(sb + AT_BYTES + stA0 + p * 4096, gB + kB + p * pStride);
        CP_COMMIT();
    }

    // ---- mainloop
    for (int it = 0; it < kiters; ++it) {
        CP_WAIT1();              // pending={it,it+1} -> stage `it` landed
        __syncthreads();         // visibility + stage it-1 slot fully drained

        const int nx = it + 2;
        if (nx < kiters) {
            const uint32_t sb = sbase + (nx % STAGES) * STG_BYTES;
            const size_t kB = (size_t)nx * 128;
            #pragma unroll
            for (int p = 0; p < 8; ++p)
                CP_ASYNC16(sb + stA0 + p * 4096, gA + kB + p * pStride);
            #pragma unroll
            for (int p = 0; p < 4; ++p)
                CP_ASYNC16(sb + AT_BYTES + stA0 + p * 4096, gB + kB + p * pStride);
        }
        CP_COMMIT();             // empty group near tail keeps wait counts aligned

        const uint32_t as = sbase + (it % STAGES) * STG_BYTES;
        const uint32_t bs = as + AT_BYTES;
        #pragma unroll
        for (int ks = 0; ks < 4; ++ks) {
            const uint32_t kb = (uint32_t)(ks * 32) + kSel;
            uint32_t a[4][4];
            #pragma unroll
            for (int mt = 0; mt < 4; ++mt) {
                // mats: {m0-7 k0-7, m8-15 k0-7, m0-7 k8-15, m8-15 k8-15}
                LDSM_X4(a[mt][0], a[mt][1], a[mt][2], a[mt][3],
                        as + aOff[mt] + (kb ^ aXor[mt]));
            }
            #pragma unroll
            for (int np = 0; np < 4; ++np) {
                // n-tile 2np: {q0,q2}, n-tile 2np+1: {q1,q3}
                uint32_t q0, q1, q2, q3;
                LDSM_X4(q0, q1, q2, q3, bs + bOff[np] + (kb ^ bXor[np]));
                #pragma unroll
                for (int mt = 0; mt < 4; ++mt) {
                    MMA16816(acc[mt][2*np][0],   acc[mt][2*np][1],
                             acc[mt][2*np][2],   acc[mt][2*np][3],
                             a[mt][0], a[mt][1], a[mt][2], a[mt][3], q0, q2);
                    MMA16816(acc[mt][2*np+1][0], acc[mt][2*np+1][1],
                             acc[mt][2*np+1][2], acc[mt][2*np+1][3],
                             a[mt][0], a[mt][1], a[mt][2], a[mt][3], q1, q3);
                }
            }
        }
    }

    // ---- epilogue: c-frag lane map: (m = lane>>2 [+8], n = (lane&3)*2)
    const int erow = m0 + wm * 64 + (lane >> 2);
    const int ecol = n0 + wn * 64 + (lane & 3) * 2;
    #pragma unroll
    for (int mt = 0; mt < 4; ++mt) {
        #pragma unroll
        for (int nt = 0; nt < 8; ++nt) {
            float* p0 = out + (size_t)(erow + mt * 16)     * N + ecol + nt * 8;
            float* p1 = out + (size_t)(erow + mt * 16 + 8) * N + ecol + nt * 8;
            *reinterpret_cast<float2*>(p0) = make_float2(acc[mt][nt][0], acc[mt][nt][1]);
            *reinterpret_cast<float2*>(p1) = make_float2(acc[mt][nt][2], acc[mt][nt][3]);
        }
    }
}

// ============================================================================
// Host: kernel_launch (graph-capturable, allocation-free)
// ============================================================================
extern "C" void kernel_launch(void* const* d_in, const int* in_sizes, int n_in,
                              void* d_out, int out_size)
{
    const float* x = (const float*)d_in[0];
    const float* w = (const float*)d_in[1];
    const int K = 4096;
    const int M = in_sizes[0] / K;   // 8192
    const int N = in_sizes[1] / K;   // 4096

    __half* Xh = nullptr;
    __half* Wh = nullptr;
    cudaGetSymbolAddress((void**)&Xh, g_Xh);
    cudaGetSymbolAddress((void**)&Wh, g_Wh);

    // 1+2: quantize->dequantize to fp16
    nvfp4_qdq_kernel<<<2048, 256>>>((const float4*)x, (uint2*)Xh, M * K / 128);
    nvfp4_qdq_kernel<<<1024, 256>>>((const float4*)w, (uint2*)Wh, N * K / 128);

    // 3: fp16 mma.sync GEMM
    cudaFuncSetAttribute(nvfp4_gemm_hmma_kernel,
                         cudaFuncAttributeMaxDynamicSharedMemorySize, SMEM_NEEDED);
    dim3 grid(M / TM, N / TN);   // (32, 32)
    nvfp4_gemm_hmma_kernel<<<grid, 256, SMEM_NEEDED>>>(
        (float*)d_out, Xh, Wh, M, N, K);
}